// round 1
// baseline (speedup 1.0000x reference)
#include <cuda_runtime.h>
#include <cuda_bf16.h>

#define S        8192
#define THREADS  1024
#define CHUNKS   (S / THREADS)      // 8 positions per thread
#define NW       (S / 32)           // 256 mask words per row
#define MAXROWS  2048

// Scratch for per-row partial results (no device allocation allowed).
__device__ float g_partial[MAXROWS];
__device__ float g_count[MAXROWS];

// Extract 11 bits for positions p-5 .. p+5 from a padded mask array.
// M is indexed with +1 offset: M[0] and M[NW+1] are zero pads.
// wi = (p>>5)+1, b = p&31. Bit k of result corresponds to position p-5+k.
__device__ __forceinline__ unsigned win11(const unsigned* M, int wi, int b) {
    if (b <= 26) {
        unsigned long long v = ((unsigned long long)M[wi] << 32) | M[wi - 1];
        // position p sits at bit 32+b of v; window starts at bit 27+b
        return (unsigned)(v >> (27 + b)) & 0x7FFu;
    } else {
        unsigned long long v = ((unsigned long long)M[wi + 1] << 32) | M[wi];
        // position p sits at bit b of v; window starts at bit b-5
        return (unsigned)(v >> (b - 5)) & 0x7FFu;
    }
}

__global__ __launch_bounds__(THREADS)
void prox_loss_row_kernel(const float4* __restrict__ logits,
                          const int*    __restrict__ labels,
                          const float*  __restrict__ cw) {
    __shared__ unsigned t2[NW + 2], t3[NW + 2], p2[NW + 2], p3[NW + 2];
    __shared__ float ws_sum[32], ws_cnt[32];

    const int row  = blockIdx.x;
    const int tid  = threadIdx.x;
    const int lane = tid & 31;
    const int warp = tid >> 5;

    if (tid == 0) {
        t2[0] = t3[0] = p2[0] = p3[0] = 0u;
        t2[NW + 1] = t3[NW + 1] = p2[NW + 1] = p3[NW + 1] = 0u;
    }

    const float w0 = __ldg(&cw[0]);
    const float w1 = __ldg(&cw[1]);
    const float w2 = __ldg(&cw[2]);
    const float w3 = __ldg(&cw[3]);

    const float4* lg = logits + (size_t)row * S;
    const int*    lb = labels + (size_t)row * S;

    float ce[CHUNKS];
    int   lab[CHUNKS];
    int   prd[CHUNKS];
    bool  hasp2 = false, hasp3 = false;

    // Phase 1: load, CE + argmax, build bitmasks via ballots.
    #pragma unroll
    for (int c = 0; c < CHUNKS; c++) {
        const int p = c * THREADS + tid;
        const float4 l = lg[p];
        const int    y = lb[p];

        // first-occurrence argmax (matches jnp.argmax)
        float m = l.x; int a = 0;
        if (l.y > m) { m = l.y; a = 1; }
        if (l.z > m) { m = l.z; a = 2; }
        if (l.w > m) { m = l.w; a = 3; }

        const float esum = expf(l.x - m) + expf(l.y - m) + expf(l.z - m) + expf(l.w - m);
        const float lse  = m + logf(esum);

        const int ys = (y < 0) ? 0 : y;
        const float ly = (ys == 0) ? l.x : (ys == 1) ? l.y : (ys == 2) ? l.z : l.w;
        const float wy = (ys == 0) ? w0  : (ys == 1) ? w1  : (ys == 2) ? w2  : w3;
        ce[c]  = (y < 0) ? 0.0f : wy * (lse - ly);
        lab[c] = y;
        prd[c] = a;

        const unsigned bt2 = __ballot_sync(0xFFFFFFFFu, y == 2);
        const unsigned bt3 = __ballot_sync(0xFFFFFFFFu, y == 3);
        const unsigned bp2 = __ballot_sync(0xFFFFFFFFu, a == 2);
        const unsigned bp3 = __ballot_sync(0xFFFFFFFFu, a == 3);
        hasp2 |= (a == 2);
        hasp3 |= (a == 3);
        if (lane == 0) {
            const int wi = (p >> 5) + 1;
            t2[wi] = bt2; t3[wi] = bt3; p2[wi] = bp2; p3[wi] = bp3;
        }
    }

    // Barrier + row-wide "any predicted switch" flags.
    const int any2 = __syncthreads_or(hasp2 ? 1 : 0);
    const int any3 = __syncthreads_or(hasp3 ? 1 : 0);

    // 0.8^d table, d = 0..5
    const float dk1 = 0.8f, dk2 = 0.64f, dk3 = 0.512f, dk4 = 0.4096f, dk5 = 0.32768f;

    float sum = 0.0f;
    float cnt = 0.0f;

    // Phase 2: window queries + weighting.
    #pragma unroll
    for (int c = 0; c < CHUNKS; c++) {
        const int p  = c * THREADS + tid;
        const int wi = (p >> 5) + 1;
        const int b  = p & 31;

        float factor = 1.0f;

        // ---- class 2 ----
        {
            const bool pm = (prd[c] == 2);
            const bool tm = (lab[c] == 2);
            if (pm) {
                const unsigned tw = win11(t2, wi, b);
                const unsigned lowerb = tw & 31u;           // p-5..p-1 (bit4 = d1)
                const unsigned upperb = (tw >> 6) & 31u;    // p+1..p+5 (bit0 = d1)
                if (!((tw >> 5) & 1u) && (lowerb | upperb)) {
                    const int dL = lowerb ? (5 - (31 - __clz(lowerb))) : 8;
                    const int dR = upperb ? __ffs(upperb) : 8;
                    const int d  = dL < dR ? dL : dR;
                    factor *= (d == 1) ? dk1 : (d == 2) ? dk2 : (d == 3) ? dk3
                                       : (d == 4) ? dk4 : dk5;
                }
            }
            if (tm) {
                if (!any2) factor *= 2.0f;
                else {
                    const unsigned pw = win11(p2, wi, b);   // includes center (d_tp = 0 ok)
                    if (!pw) factor *= 1.5f;
                }
            }
        }

        // ---- class 3 ----
        {
            const bool pm = (prd[c] == 3);
            const bool tm = (lab[c] == 3);
            if (pm) {
                const unsigned tw = win11(t3, wi, b);
                const unsigned lowerb = tw & 31u;
                const unsigned upperb = (tw >> 6) & 31u;
                if (!((tw >> 5) & 1u) && (lowerb | upperb)) {
                    const int dL = lowerb ? (5 - (31 - __clz(lowerb))) : 8;
                    const int dR = upperb ? __ffs(upperb) : 8;
                    const int d  = dL < dR ? dL : dR;
                    factor *= (d == 1) ? dk1 : (d == 2) ? dk2 : (d == 3) ? dk3
                                       : (d == 4) ? dk4 : dk5;
                }
            }
            if (tm) {
                if (!any3) factor *= 2.0f;
                else {
                    const unsigned pw = win11(p3, wi, b);
                    if (!pw) factor *= 1.5f;
                }
            }
        }

        sum += ce[c] * factor;
        cnt += (lab[c] >= 0) ? 1.0f : 0.0f;
    }

    // Block reduction.
    #pragma unroll
    for (int o = 16; o > 0; o >>= 1) {
        sum += __shfl_down_sync(0xFFFFFFFFu, sum, o);
        cnt += __shfl_down_sync(0xFFFFFFFFu, cnt, o);
    }
    if (lane == 0) { ws_sum[warp] = sum; ws_cnt[warp] = cnt; }
    __syncthreads();
    if (warp == 0) {
        sum = ws_sum[lane];
        cnt = ws_cnt[lane];
        #pragma unroll
        for (int o = 16; o > 0; o >>= 1) {
            sum += __shfl_down_sync(0xFFFFFFFFu, sum, o);
            cnt += __shfl_down_sync(0xFFFFFFFFu, cnt, o);
        }
        if (lane == 0) { g_partial[row] = sum; g_count[row] = cnt; }
    }
}

__global__ void prox_loss_reduce_kernel(float* __restrict__ out, int nrows) {
    __shared__ float ws_sum[32], ws_cnt[32];
    const int tid  = threadIdx.x;
    const int lane = tid & 31;
    const int warp = tid >> 5;

    float s = 0.0f, c = 0.0f;
    for (int i = tid; i < nrows; i += blockDim.x) {
        s += g_partial[i];
        c += g_count[i];
    }
    #pragma unroll
    for (int o = 16; o > 0; o >>= 1) {
        s += __shfl_down_sync(0xFFFFFFFFu, s, o);
        c += __shfl_down_sync(0xFFFFFFFFu, c, o);
    }
    if (lane == 0) { ws_sum[warp] = s; ws_cnt[warp] = c; }
    __syncthreads();
    if (warp == 0) {
        s = (lane < (int)(blockDim.x >> 5)) ? ws_sum[lane] : 0.0f;
        c = (lane < (int)(blockDim.x >> 5)) ? ws_cnt[lane] : 0.0f;
        #pragma unroll
        for (int o = 16; o > 0; o >>= 1) {
            s += __shfl_down_sync(0xFFFFFFFFu, s, o);
            c += __shfl_down_sync(0xFFFFFFFFu, c, o);
        }
        if (lane == 0) out[0] = s / fmaxf(c, 1.0f);
    }
}

extern "C" void kernel_launch(void* const* d_in, const int* in_sizes, int n_in,
                              void* d_out, int out_size) {
    const float4* logits = (const float4*)d_in[0];
    const int*    labels = (const int*)d_in[1];
    const float*  cw     = (const float*)d_in[2];
    float*        out    = (float*)d_out;

    const int nrows = in_sizes[1] / S;   // B = 512 for this problem

    prox_loss_row_kernel<<<nrows, THREADS>>>(logits, labels, cw);
    prox_loss_reduce_kernel<<<1, 512>>>(out, nrows);
}

// round 2
// speedup vs baseline: 1.0487x; 1.0487x over previous
#include <cuda_runtime.h>
#include <cuda_bf16.h>

#define S        8192
#define THREADS  1024
#define CHUNKS   (S / THREADS)      // 8 positions per thread
#define NW       (S / 32)           // 256 mask words per row
#define MAXROWS  2048

// Scratch for per-row partial results + completion counter (no device allocs).
__device__ float    g_partial[MAXROWS];
__device__ float    g_count[MAXROWS];
__device__ unsigned g_done;          // zero-init; self-resets each pass

// Extract 11 bits for positions p-5 .. p+5 from a padded mask array.
// M indexed with +1 offset: M[0] and M[NW+1] are zero pads.
// wi = (p>>5)+1, b = p&31. Bit k of result = position p-5+k. Center = bit 5.
__device__ __forceinline__ unsigned win11(const unsigned* M, int wi, int b) {
    if (b <= 26) {
        unsigned long long v = ((unsigned long long)M[wi] << 32) | M[wi - 1];
        return (unsigned)(v >> (27 + b)) & 0x7FFu;
    } else {
        unsigned long long v = ((unsigned long long)M[wi + 1] << 32) | M[wi];
        return (unsigned)(v >> (b - 5)) & 0x7FFu;
    }
}

__global__ __launch_bounds__(THREADS)
void prox_loss_kernel(const float4* __restrict__ logits,
                      const int*    __restrict__ labels,
                      const float*  __restrict__ cw,
                      float*        __restrict__ out,
                      int nrows) {
    __shared__ float    ce_s[S];                       // 32 KB
    __shared__ unsigned t2[NW + 2], t3[NW + 2], p2[NW + 2], p3[NW + 2];
    __shared__ float    ws_sum[32], ws_cnt[32];
    __shared__ bool     s_is_last;

    const int row  = blockIdx.x;
    const int tid  = threadIdx.x;
    const int lane = tid & 31;
    const int warp = tid >> 5;

    if (tid == 0) {
        t2[0] = t3[0] = p2[0] = p3[0] = 0u;
        t2[NW + 1] = t3[NW + 1] = p2[NW + 1] = p3[NW + 1] = 0u;
    }

    const float w0 = __ldg(&cw[0]);
    const float w1 = __ldg(&cw[1]);
    const float w2 = __ldg(&cw[2]);
    const float w3 = __ldg(&cw[3]);

    const float4* lg = logits + (size_t)row * S;
    const int*    lb = labels + (size_t)row * S;

    float cnt = 0.0f;
    bool  hasp2 = false, hasp3 = false;

    // ---- Phase 1: load, CE (to smem) + argmax, ballot masks. No register
    //      arrays survive the barrier. ----
    #pragma unroll
    for (int c = 0; c < CHUNKS; c++) {
        const int p = c * THREADS + tid;
        const float4 l = lg[p];
        const int    y = lb[p];

        // first-occurrence argmax (matches jnp.argmax)
        float m = l.x; int a = 0;
        if (l.y > m) { m = l.y; a = 1; }
        if (l.z > m) { m = l.z; a = 2; }
        if (l.w > m) { m = l.w; a = 3; }

        const float esum = __expf(l.x - m) + __expf(l.y - m)
                         + __expf(l.z - m) + __expf(l.w - m);
        const float lse  = m + __logf(esum);

        const int ys = (y < 0) ? 0 : y;
        const float ly = (ys == 0) ? l.x : (ys == 1) ? l.y : (ys == 2) ? l.z : l.w;
        const float wy = (ys == 0) ? w0  : (ys == 1) ? w1  : (ys == 2) ? w2  : w3;
        ce_s[p] = (y < 0) ? 0.0f : wy * (lse - ly);
        cnt += (y >= 0) ? 1.0f : 0.0f;

        const unsigned bt2 = __ballot_sync(0xFFFFFFFFu, y == 2);
        const unsigned bt3 = __ballot_sync(0xFFFFFFFFu, y == 3);
        const unsigned bp2 = __ballot_sync(0xFFFFFFFFu, a == 2);
        const unsigned bp3 = __ballot_sync(0xFFFFFFFFu, a == 3);
        hasp2 |= (a == 2);
        hasp3 |= (a == 3);
        if (lane == 0) {
            const int wi = (p >> 5) + 1;
            t2[wi] = bt2; t3[wi] = bt3; p2[wi] = bp2; p3[wi] = bp3;
        }
    }

    const int any2 = __syncthreads_or(hasp2 ? 1 : 0);
    const int any3 = __syncthreads_or(hasp3 ? 1 : 0);

    // 0.8^d, d = 1..5
    const float dk1 = 0.8f, dk2 = 0.64f, dk3 = 0.512f, dk4 = 0.4096f, dk5 = 0.32768f;

    float sum = 0.0f;

    // ---- Phase 2: window queries from smem masks (warp-uniform -> broadcast),
    //      membership re-derived from center bits. ----
    #pragma unroll
    for (int c = 0; c < CHUNKS; c++) {
        const int p  = c * THREADS + tid;
        const int wi = (p >> 5) + 1;
        const int b  = p & 31;

        const unsigned tw2 = win11(t2, wi, b);
        const unsigned pw2 = win11(p2, wi, b);
        const unsigned tw3 = win11(t3, wi, b);
        const unsigned pw3 = win11(p3, wi, b);

        float factor = 1.0f;

        // ---- class 2 ----
        if ((pw2 >> 5) & 1u) {                       // predicted switch here
            const unsigned lowerb = tw2 & 31u;       // p-5..p-1 (bit4 = d1)
            const unsigned upperb = (tw2 >> 6) & 31u;// p+1..p+5 (bit0 = d1)
            if (!((tw2 >> 5) & 1u) && (lowerb | upperb)) {
                const int dL = lowerb ? (5 - (31 - __clz(lowerb))) : 8;
                const int dR = upperb ? __ffs(upperb) : 8;
                const int d  = dL < dR ? dL : dR;
                factor *= (d == 1) ? dk1 : (d == 2) ? dk2 : (d == 3) ? dk3
                                   : (d == 4) ? dk4 : dk5;
            }
        }
        if ((tw2 >> 5) & 1u) {                       // true switch here
            if (!any2)        factor *= 2.0f;
            else if (!pw2)    factor *= 1.5f;        // window incl. center
        }

        // ---- class 3 ----
        if ((pw3 >> 5) & 1u) {
            const unsigned lowerb = tw3 & 31u;
            const unsigned upperb = (tw3 >> 6) & 31u;
            if (!((tw3 >> 5) & 1u) && (lowerb | upperb)) {
                const int dL = lowerb ? (5 - (31 - __clz(lowerb))) : 8;
                const int dR = upperb ? __ffs(upperb) : 8;
                const int d  = dL < dR ? dL : dR;
                factor *= (d == 1) ? dk1 : (d == 2) ? dk2 : (d == 3) ? dk3
                                   : (d == 4) ? dk4 : dk5;
            }
        }
        if ((tw3 >> 5) & 1u) {
            if (!any3)        factor *= 2.0f;
            else if (!pw3)    factor *= 1.5f;
        }

        sum += ce_s[p] * factor;
    }

    // ---- Block reduction ----
    #pragma unroll
    for (int o = 16; o > 0; o >>= 1) {
        sum += __shfl_down_sync(0xFFFFFFFFu, sum, o);
        cnt += __shfl_down_sync(0xFFFFFFFFu, cnt, o);
    }
    if (lane == 0) { ws_sum[warp] = sum; ws_cnt[warp] = cnt; }
    __syncthreads();
    if (warp == 0) {
        sum = ws_sum[lane];
        cnt = ws_cnt[lane];
        #pragma unroll
        for (int o = 16; o > 0; o >>= 1) {
            sum += __shfl_down_sync(0xFFFFFFFFu, sum, o);
            cnt += __shfl_down_sync(0xFFFFFFFFu, cnt, o);
        }
        if (lane == 0) {
            g_partial[row] = sum;
            g_count[row]   = cnt;
            __threadfence();
            const unsigned prev = atomicAdd(&g_done, 1u);
            s_is_last = (prev == (unsigned)(nrows - 1));
        }
    }
    __syncthreads();

    // ---- Last block finishes: global reduce + divide, reset counter ----
    if (s_is_last) {
        float s = 0.0f, c = 0.0f;
        for (int i = tid; i < nrows; i += THREADS) {
            s += *((volatile float*)&g_partial[i]);
            c += *((volatile float*)&g_count[i]);
        }
        #pragma unroll
        for (int o = 16; o > 0; o >>= 1) {
            s += __shfl_down_sync(0xFFFFFFFFu, s, o);
            c += __shfl_down_sync(0xFFFFFFFFu, c, o);
        }
        if (lane == 0) { ws_sum[warp] = s; ws_cnt[warp] = c; }
        __syncthreads();
        if (warp == 0) {
            s = ws_sum[lane];
            c = ws_cnt[lane];
            #pragma unroll
            for (int o = 16; o > 0; o >>= 1) {
                s += __shfl_down_sync(0xFFFFFFFFu, s, o);
                c += __shfl_down_sync(0xFFFFFFFFu, c, o);
            }
            if (lane == 0) {
                out[0]  = s / fmaxf(c, 1.0f);
                g_done  = 0u;                 // reset for next graph replay
            }
        }
    }
}

extern "C" void kernel_launch(void* const* d_in, const int* in_sizes, int n_in,
                              void* d_out, int out_size) {
    const float4* logits = (const float4*)d_in[0];
    const int*    labels = (const int*)d_in[1];
    const float*  cw     = (const float*)d_in[2];
    float*        out    = (float*)d_out;

    const int nrows = in_sizes[1] / S;   // B = 512 for this problem

    prox_loss_kernel<<<nrows, THREADS>>>(logits, labels, cw, out, nrows);
}

// round 3
// speedup vs baseline: 1.9044x; 1.8159x over previous
#include <cuda_runtime.h>
#include <cuda_bf16.h>

#define S        8192
#define TPB      256
#define CHUNKS   (S / TPB)          // 32 positions per thread
#define NW       (S / 32)           // 256 mask words per row
#define MAXROWS  2048

__device__ float    g_partial[MAXROWS];
__device__ float    g_count[MAXROWS];
__device__ unsigned g_done;          // zero-init; self-resets every pass

__global__ __launch_bounds__(TPB, 6)
void prox_loss_kernel(const float4* __restrict__ logits,
                      const int*    __restrict__ labels,
                      const float*  __restrict__ cw,
                      float*        __restrict__ out,
                      int nrows) {
    __shared__ float    ce_s[S];                        // 32 KB
    __shared__ unsigned t2[NW + 2], t3[NW + 2], p2[NW + 2], p3[NW + 2];
    __shared__ float    ws_sum[TPB / 32], ws_cnt[TPB / 32];
    __shared__ bool     s_is_last;

    const int row  = blockIdx.x;
    const int tid  = threadIdx.x;
    const int lane = tid & 31;
    const int warp = tid >> 5;

    if (tid == 0) {
        t2[0] = t3[0] = p2[0] = p3[0] = 0u;
        t2[NW + 1] = t3[NW + 1] = p2[NW + 1] = p3[NW + 1] = 0u;
    }

    const float w0 = __ldg(&cw[0]);
    const float w1 = __ldg(&cw[1]);
    const float w2 = __ldg(&cw[2]);
    const float w3 = __ldg(&cw[3]);

    const float4* lg = logits + (size_t)row * S;
    const int*    lb = labels + (size_t)row * S;

    float cnt = 0.0f;
    bool  hasp2 = false, hasp3 = false;

    // ---- Phase 1: load, CE -> smem, argmax, ballot masks -> smem ----
    #pragma unroll 4
    for (int c = 0; c < CHUNKS; c++) {
        const int p = c * TPB + tid;
        const float4 l = lg[p];
        const int    y = lb[p];

        // first-occurrence argmax (matches jnp.argmax)
        float m = l.x; int a = 0;
        if (l.y > m) { m = l.y; a = 1; }
        if (l.z > m) { m = l.z; a = 2; }
        if (l.w > m) { m = l.w; a = 3; }

        const float esum = __expf(l.x - m) + __expf(l.y - m)
                         + __expf(l.z - m) + __expf(l.w - m);
        const float lse  = m + __logf(esum);

        const int ys = (y < 0) ? 0 : y;
        const float ly = (ys == 0) ? l.x : (ys == 1) ? l.y : (ys == 2) ? l.z : l.w;
        const float wy = (ys == 0) ? w0  : (ys == 1) ? w1  : (ys == 2) ? w2  : w3;
        ce_s[p] = (y < 0) ? 0.0f : wy * (lse - ly);
        cnt += (y >= 0) ? 1.0f : 0.0f;

        const unsigned bt2 = __ballot_sync(0xFFFFFFFFu, y == 2);
        const unsigned bt3 = __ballot_sync(0xFFFFFFFFu, y == 3);
        const unsigned bp2 = __ballot_sync(0xFFFFFFFFu, a == 2);
        const unsigned bp3 = __ballot_sync(0xFFFFFFFFu, a == 3);
        hasp2 |= (a == 2);
        hasp3 |= (a == 3);
        if (lane == 0) {
            const int wi = (p >> 5) + 1;
            t2[wi] = bt2; t3[wi] = bt3; p2[wi] = bp2; p3[wi] = bp3;
        }
    }

    const int any2 = __syncthreads_or(hasp2 ? 1 : 0);
    const int any3 = __syncthreads_or(hasp3 ? 1 : 0);

    const float NEG_LOG2_08 = -0.321928095f;   // log2(0.8)
    float sum = 0.0f;

    // ---- Phase 2: branchless window queries ----
    #pragma unroll 4
    for (int c = 0; c < CHUNKS; c++) {
        const int p  = c * TPB + tid;
        const int wi = (p >> 5) + 1;   // warp-uniform
        const int b  = p & 31;         // = lane

        // center bits (4 broadcast LDS)
        const unsigned wt2 = t2[wi], wt3 = t3[wi];
        const unsigned wp2 = p2[wi], wp3 = p3[wi];
        const unsigned y2 = (wt2 >> b) & 1u, y3 = (wt3 >> b) & 1u;
        const unsigned a2 = (wp2 >> b) & 1u, a3 = (wp3 >> b) & 1u;

        // 11-bit window: bits [p-5 .. p+5] in padded bitspace, start = p+27
        const int bp  = p + 27;
        const int wi0 = bp >> 5;
        const int sh  = bp & 31;

        // true-mask window of the PREDICTED class (for decay)
        const unsigned* Tm = a3 ? t3 : t2;
        const unsigned tw = __funnelshift_r(Tm[wi0], Tm[wi0 + 1], sh) & 0x7FFu;
        // pred-mask window of the LABEL class (for tfac); includes center
        const unsigned* Pm = y3 ? p3 : p2;
        const unsigned pw = __funnelshift_r(Pm[wi0], Pm[wi0 + 1], sh) & 0x7FFu;

        // decay = 0.8^d, d = min dist to true switch (excl. center), d in 1..5
        const unsigned lower = tw & 31u;            // p-5..p-1, bit4 = d1
        const unsigned upper = (tw >> 6) & 31u;     // p+1..p+5, bit0 = d1
        const unsigned twc   = (tw >> 5) & 1u;
        const unsigned fold  = (__brev(lower) >> 27) | upper;  // bit(k-1) = dist k
        const int   d     = __ffs(fold);            // 1..5 when fold != 0
        const float decay = exp2f((float)d * NEG_LOG2_08);
        const bool  dap   = (a2 | a3) && !twc && fold;
        const float f1    = dap ? decay : 1.0f;

        // tfac
        const bool tm   = (y2 | y3);
        const int  anyc = y3 ? any3 : any2;
        const float f2  = tm ? (anyc ? (pw ? 1.0f : 1.5f) : 2.0f) : 1.0f;

        sum += ce_s[p] * (f1 * f2);
    }

    // ---- Block reduction ----
    #pragma unroll
    for (int o = 16; o > 0; o >>= 1) {
        sum += __shfl_down_sync(0xFFFFFFFFu, sum, o);
        cnt += __shfl_down_sync(0xFFFFFFFFu, cnt, o);
    }
    if (lane == 0) { ws_sum[warp] = sum; ws_cnt[warp] = cnt; }
    __syncthreads();
    if (warp == 0) {
        sum = (lane < TPB / 32) ? ws_sum[lane] : 0.0f;
        cnt = (lane < TPB / 32) ? ws_cnt[lane] : 0.0f;
        #pragma unroll
        for (int o = 4; o > 0; o >>= 1) {
            sum += __shfl_down_sync(0xFFFFFFFFu, sum, o);
            cnt += __shfl_down_sync(0xFFFFFFFFu, cnt, o);
        }
        if (lane == 0) {
            g_partial[row] = sum;
            g_count[row]   = cnt;
            __threadfence();
            const unsigned prev = atomicAdd(&g_done, 1u);
            s_is_last = (prev == (unsigned)(nrows - 1));
        }
    }
    __syncthreads();

    // ---- Last block: global reduce + divide, reset counter ----
    if (s_is_last) {
        float s = 0.0f, c = 0.0f;
        for (int i = tid; i < nrows; i += TPB) {
            s += *((volatile float*)&g_partial[i]);
            c += *((volatile float*)&g_count[i]);
        }
        #pragma unroll
        for (int o = 16; o > 0; o >>= 1) {
            s += __shfl_down_sync(0xFFFFFFFFu, s, o);
            c += __shfl_down_sync(0xFFFFFFFFu, c, o);
        }
        if (lane == 0) { ws_sum[warp] = s; ws_cnt[warp] = c; }
        __syncthreads();
        if (warp == 0) {
            s = (lane < TPB / 32) ? ws_sum[lane] : 0.0f;
            c = (lane < TPB / 32) ? ws_cnt[lane] : 0.0f;
            #pragma unroll
            for (int o = 4; o > 0; o >>= 1) {
                s += __shfl_down_sync(0xFFFFFFFFu, s, o);
                c += __shfl_down_sync(0xFFFFFFFFu, c, o);
            }
            if (lane == 0) {
                out[0] = s / fmaxf(c, 1.0f);
                g_done = 0u;
            }
        }
    }
}

extern "C" void kernel_launch(void* const* d_in, const int* in_sizes, int n_in,
                              void* d_out, int out_size) {
    const float4* logits = (const float4*)d_in[0];
    const int*    labels = (const int*)d_in[1];
    const float*  cw     = (const float*)d_in[2];
    float*        out    = (float*)d_out;

    const int nrows = in_sizes[1] / S;   // B = 512

    prox_loss_kernel<<<nrows, TPB>>>(logits, labels, cw, out, nrows);
}